// round 5
// baseline (speedup 1.0000x reference)
#include <cuda_runtime.h>

#define Wd 512
#define Hd 256
#define Bd 4
#define HW (Hd*Wd)
#define NP (Bd*HW)

// k_pre: 32x16 pixel tile, V=2 pixels/thread (block 32x8)
#define PTX 32
#define PTY 8
#define PVY 2
#define PTILEH (PTY*PVY)   // 16
#define PSW (PTX+4)        // 36
#define PSH (PTILEH+4)     // 20

// k_iter: 32x32 pixel tile, V=4 pixels/thread (block 32x8)
#define ITX 32
#define ITY 8
#define IVY 4
#define ITILEH (ITY*IVY)   // 32
#define ISW (ITX+4)        // 36
#define ISH (ITILEH+4)     // 36

// Scratch (static __device__ arrays; no cudaMalloc allowed)
__device__ float g_w[25*NP];   // raw bilateral weights (iteration-invariant)
__device__ float g_M[7*NP];    // 6 planes Mtilde (sym) + plane 6 = invsum
__device__ float g_PA[3*NP];
__device__ float g_PB[3*NP];

// ---------------------------------------------------------------------------
// k_pre: weights + Mtilde + invsum + first iteration (P1 = P0 + imp0)
// ---------------------------------------------------------------------------
__global__ __launch_bounds__(256) void k_pre(const float* __restrict__ pts,
                                             const float* __restrict__ nrm,
                                             float* __restrict__ P1)
{
    __shared__ float4 sP [PSH][PSW];   // (Px,Py,Pz,_)
    __shared__ float4 sND[PSH][PSW];   // (Nx,Ny,Nz,D)
    const int b  = blockIdx.z;
    const int x0 = blockIdx.x*PTX, y0 = blockIdx.y*PTILEH;
    const float* pb = pts + b*3*HW;
    const float* nb = nrm + b*3*HW;

    for (int i = threadIdx.y*PTX + threadIdx.x; i < PSW*PSH; i += PTX*PTY) {
        int cy = i/PSW, cx = i - cy*PSW;
        int gx = x0+cx-2, gy = y0+cy-2;
        float px=0.f,py=0.f,pz=0.f,nx=0.f,ny=0.f,nz=0.f;
        if ((unsigned)gx < Wd && (unsigned)gy < Hd) {
            int o = gy*Wd + gx;
            px = pb[o]; py = pb[o+HW]; pz = pb[o+2*HW];
            nx = nb[o]; ny = nb[o+HW]; nz = nb[o+2*HW];
        }
        sP [cy][cx] = make_float4(px,py,pz,0.f);
        sND[cy][cx] = make_float4(nx,ny,nz, px*nx + py*ny + pz*nz);
    }
    __syncthreads();

    const int tx = threadIdx.x, ty = threadIdx.y;
    const int r0 = ty*PVY;

    float cpx[PVY], cpy[PVY], cpz[PVY];
    float cnx[PVY], cny[PVY], cnz[PVY];
    #pragma unroll
    for (int p = 0; p < PVY; p++) {
        float4 pc = sP [r0+p+2][tx+2];
        float4 nc = sND[r0+p+2][tx+2];
        cpx[p]=pc.x; cpy[p]=pc.y; cpz[p]=pc.z;
        cnx[p]=nc.x; cny[p]=nc.y; cnz[p]=nc.z;
    }

    // Pass 1: squared distances per tap, per pixel; running max for sigma_c
    float wv[PVY][25];
    float maxn2[PVY];
    #pragma unroll
    for (int p = 0; p < PVY; p++) maxn2[p] = 0.f;
    #pragma unroll
    for (int j = 0; j < PVY+4; j++) {
        #pragma unroll
        for (int dx = 0; dx < 5; dx++) {
            float4 pv = sP[r0+j][tx+dx];
            #pragma unroll
            for (int p = 0; p < PVY; p++) {
                int dyk = j - p;
                if (dyk >= 0 && dyk <= 4) {
                    float a = pv.x - cpx[p], bq = pv.y - cpy[p], c = pv.z - cpz[p];
                    float d2 = a*a + bq*bq + c*c;
                    wv[p][dyk*5+dx] = d2;
                    maxn2[p] = fmaxf(maxn2[p], d2);
                }
            }
        }
    }
    float nscale[PVY];
    #pragma unroll
    for (int p = 0; p < PVY; p++) {
        float sig = sqrtf(maxn2[p])*0.2f + 1e-5f;
        nscale[p] = -0.5f/(sig*sig);
    }

    // Pass 2: w = exp(nscale*d2 - 4.5*(1-cos)^2); accumulate wsum, v, M
    const int gx = x0+tx;
    int pixid[PVY];
    #pragma unroll
    for (int p = 0; p < PVY; p++) pixid[p] = (b*Hd + y0+r0+p)*Wd + gx;

    float wsum[PVY], vx[PVY], vy[PVY], vz[PVY];
    float M00[PVY],M01[PVY],M02[PVY],M11[PVY],M12[PVY],M22[PVY];
    #pragma unroll
    for (int p = 0; p < PVY; p++) {
        wsum[p]=0.f; vx[p]=0.f; vy[p]=0.f; vz[p]=0.f;
        M00[p]=0.f;M01[p]=0.f;M02[p]=0.f;M11[p]=0.f;M12[p]=0.f;M22[p]=0.f;
    }
    #pragma unroll
    for (int j = 0; j < PVY+4; j++) {
        #pragma unroll
        for (int dx = 0; dx < 5; dx++) {
            float4 nd = sND[r0+j][tx+dx];
            #pragma unroll
            for (int p = 0; p < PVY; p++) {
                int dyk = j - p;
                if (dyk >= 0 && dyk <= 4) {
                    int k = dyk*5 + dx;
                    float cosv = cnx[p]*nd.x + cny[p]*nd.y + cnz[p]*nd.z;
                    float e = 1.f - cosv;
                    float w = __expf(wv[p][k]*nscale[p] - 4.5f*e*e);
                    g_w[k*NP + pixid[p]] = w;
                    wsum[p] += w;
                    float s = w*nd.w;
                    vx[p] += s*nd.x; vy[p] += s*nd.y; vz[p] += s*nd.z;
                    float t0 = w*nd.x;
                    M00[p] += t0*nd.x; M01[p] += t0*nd.y; M02[p] += t0*nd.z;
                    float t1 = w*nd.y;
                    M11[p] += t1*nd.y; M12[p] += t1*nd.z;
                    M22[p] += w*nd.z*nd.z;
                }
            }
        }
    }
    #pragma unroll
    for (int p = 0; p < PVY; p++) {
        float invsum = 1.f/wsum[p];
        int id = pixid[p];
        float m00=M00[p]*invsum, m01=M01[p]*invsum, m02=M02[p]*invsum;
        float m11=M11[p]*invsum, m12=M12[p]*invsum, m22=M22[p]*invsum;
        g_M[0*NP+id]=m00; g_M[1*NP+id]=m01; g_M[2*NP+id]=m02;
        g_M[3*NP+id]=m11; g_M[4*NP+id]=m12; g_M[5*NP+id]=m22;
        g_M[6*NP+id]=invsum;
        float ix = invsum*vx[p] - (m00*cpx[p] + m01*cpy[p] + m02*cpz[p]);
        float iy = invsum*vy[p] - (m01*cpx[p] + m11*cpy[p] + m12*cpz[p]);
        float iz = invsum*vz[p] - (m02*cpx[p] + m12*cpy[p] + m22*cpz[p]);
        int o = b*3*HW + (y0+r0+p)*Wd + gx;
        P1[o]      = cpx[p] + ix;
        P1[o+HW]   = cpy[p] + iy;
        P1[o+2*HW] = cpz[p] + iz;
    }
}

// ---------------------------------------------------------------------------
// k_iter: P_out = P_cur + invsum*sum_k w_k D_k N_k - Mt*P_cur   (D_k = N_k.P_k)
// ---------------------------------------------------------------------------
template<bool LAST>
__global__ __launch_bounds__(256) void k_iter(const float* __restrict__ Pcur,
                                              const float* __restrict__ nrm,
                                              const float* __restrict__ ptsOrig,
                                              float* __restrict__ Pout)
{
    __shared__ float4 sND[ISH][ISW];   // (Nx,Ny,Nz,D) with D = N.Pcur
    const int b  = blockIdx.z;
    const int x0 = blockIdx.x*ITX, y0 = blockIdx.y*ITILEH;
    const float* pb = Pcur + b*3*HW;
    const float* nb = nrm  + b*3*HW;

    for (int i = threadIdx.y*ITX + threadIdx.x; i < ISW*ISH; i += ITX*ITY) {
        int cy = i/ISW, cx = i - cy*ISW;
        int gx = x0+cx-2, gy = y0+cy-2;
        float px=0.f,py=0.f,pz=0.f,nx=0.f,ny=0.f,nz=0.f;
        if ((unsigned)gx < Wd && (unsigned)gy < Hd) {
            int o = gy*Wd + gx;
            px = pb[o]; py = pb[o+HW]; pz = pb[o+2*HW];
            nx = nb[o]; ny = nb[o+HW]; nz = nb[o+2*HW];
        }
        sND[cy][cx] = make_float4(nx,ny,nz, px*nx + py*ny + pz*nz);
    }
    __syncthreads();

    const int tx = threadIdx.x, ty = threadIdx.y;
    const int r0 = ty*IVY;
    const int gx = x0+tx;

    int pixid[IVY], o[IVY];
    float cpx[IVY], cpy[IVY], cpz[IVY];
    float vx[IVY], vy[IVY], vz[IVY];
    #pragma unroll
    for (int p = 0; p < IVY; p++) {
        int gy = y0 + r0 + p;
        pixid[p] = (b*Hd + gy)*Wd + gx;
        o[p] = b*3*HW + gy*Wd + gx;
        cpx[p] = Pcur[o[p]]; cpy[p] = Pcur[o[p]+HW]; cpz[p] = Pcur[o[p]+2*HW];
        vx[p]=0.f; vy[p]=0.f; vz[p]=0.f;
    }

    #pragma unroll
    for (int j = 0; j < IVY+4; j++) {
        #pragma unroll
        for (int dx = 0; dx < 5; dx++) {
            float4 nd = sND[r0+j][tx+dx];
            #pragma unroll
            for (int p = 0; p < IVY; p++) {
                int dyk = j - p;
                if (dyk >= 0 && dyk <= 4) {
                    float w = g_w[(dyk*5+dx)*NP + pixid[p]];
                    float s = w*nd.w;
                    vx[p] += s*nd.x; vy[p] += s*nd.y; vz[p] += s*nd.z;
                }
            }
        }
    }

    #pragma unroll
    for (int p = 0; p < IVY; p++) {
        int id = pixid[p];
        float m00=g_M[0*NP+id], m01=g_M[1*NP+id], m02=g_M[2*NP+id];
        float m11=g_M[3*NP+id], m12=g_M[4*NP+id], m22=g_M[5*NP+id];
        float invsum = g_M[6*NP+id];
        float ox = cpx[p] + invsum*vx[p] - (m00*cpx[p] + m01*cpy[p] + m02*cpz[p]);
        float oy = cpy[p] + invsum*vy[p] - (m01*cpx[p] + m11*cpy[p] + m12*cpz[p]);
        float oz = cpz[p] + invsum*vz[p] - (m02*cpx[p] + m12*cpy[p] + m22*cpz[p]);
        if (LAST) {
            ox = (ptsOrig[o[p]]      != 0.f) ? ox : 0.f;
            oy = (ptsOrig[o[p]+HW]   != 0.f) ? oy : 0.f;
            oz = (ptsOrig[o[p]+2*HW] != 0.f) ? oz : 0.f;
        }
        Pout[o[p]] = ox; Pout[o[p]+HW] = oy; Pout[o[p]+2*HW] = oz;
    }
}

extern "C" void kernel_launch(void* const* d_in, const int* in_sizes, int n_in,
                              void* d_out, int out_size)
{
    const float* pts = (const float*)d_in[0];
    const float* nrm = (const float*)d_in[1];
    float* out = (float*)d_out;

    float *PA, *PB;
    cudaGetSymbolAddress((void**)&PA, g_PA);
    cudaGetSymbolAddress((void**)&PB, g_PB);

    dim3 pblock(PTX, PTY);
    dim3 pgrid(Wd/PTX, Hd/PTILEH, Bd);    // 16 x 16 x 4

    dim3 iblock(ITX, ITY);
    dim3 igrid(Wd/ITX, Hd/ITILEH, Bd);    // 16 x 8 x 4

    k_pre<<<pgrid, pblock>>>(pts, nrm, PA);               // weights + M + iter 1
    k_iter<false><<<igrid, iblock>>>(PA, nrm, pts, PB);   // iter 2
    k_iter<true ><<<igrid, iblock>>>(PB, nrm, pts, out);  // iter 3 + mask
}

// round 6
// speedup vs baseline: 1.3696x; 1.3696x over previous
#include <cuda_runtime.h>

#define Wd 512
#define Hd 256
#define Bd 4
#define HW (Hd*Wd)
#define NP (Bd*HW)
#define TX 32
#define TY 8
#define HALO 2
#define SWd (TX+2*HALO)   // 36
#define SHd (TY+2*HALO)   // 12

// Scratch (static __device__ arrays; no cudaMalloc allowed)
__device__ float4 g_w4[6*NP];  // weights k=0..23 packed as float4 planes (50 MB)
__device__ float  g_w1[NP];    // weight k=24
__device__ float  g_is[NP];    // 1/sum(w)
__device__ float  g_PA[3*NP];
__device__ float  g_PB[3*NP];

// ---------------------------------------------------------------------------
// k_pre: bilateral weights (iteration-invariant, stored raw + invsum) and
// first smoothing iteration P1 = P0 + imp0.   (R2 structure, vector stores)
// ---------------------------------------------------------------------------
__global__ __launch_bounds__(256) void k_pre(const float* __restrict__ pts,
                                             const float* __restrict__ nrm,
                                             float* __restrict__ P1)
{
    __shared__ float4 sP [SHd][SWd];   // (Px,Py,Pz,_)
    __shared__ float4 sND[SHd][SWd];   // (Nx,Ny,Nz,D)
    const int b  = blockIdx.z;
    const int x0 = blockIdx.x*TX, y0 = blockIdx.y*TY;
    const float* pb = pts + b*3*HW;
    const float* nb = nrm + b*3*HW;

    for (int i = threadIdx.y*TX + threadIdx.x; i < SWd*SHd; i += TX*TY) {
        int cy = i/SWd, cx = i - cy*SWd;
        int gx = x0+cx-HALO, gy = y0+cy-HALO;
        float px=0.f,py=0.f,pz=0.f,nx=0.f,ny=0.f,nz=0.f;
        if ((unsigned)gx < Wd && (unsigned)gy < Hd) {
            int o = gy*Wd + gx;
            px = pb[o]; py = pb[o+HW]; pz = pb[o+2*HW];
            nx = nb[o]; ny = nb[o+HW]; nz = nb[o+2*HW];
        }
        sP [cy][cx] = make_float4(px,py,pz,0.f);
        sND[cy][cx] = make_float4(nx,ny,nz, px*nx + py*ny + pz*nz);
    }
    __syncthreads();

    const int tx = threadIdx.x, ty = threadIdx.y;
    const int cx = tx+HALO,   cy = ty+HALO;
    const float4 pc = sP[cy][cx];
    const float4 nc = sND[cy][cx];
    const float pix_ = pc.x, piy = pc.y, piz = pc.z;
    const float nix  = nc.x, niy = nc.y, niz = nc.z;

    // Pass 1: squared point distances + running max (for sigma_c)
    float wv[25];
    float maxn2 = 0.f;
    #pragma unroll
    for (int k = 0; k < 25; k++) {
        int dy = k/5 - 2, dx = k%5 - 2;
        float4 p = sP[cy+dy][cx+dx];
        float a = p.x - pix_, bq = p.y - piy, c = p.z - piz;
        float d2 = a*a + bq*bq + c*c;
        wv[k] = d2;
        maxn2 = fmaxf(maxn2, d2);
    }
    float sig    = sqrtf(maxn2)*0.2f + 1e-5f;
    float nscale = -0.5f/(sig*sig);

    // Pass 2: w = exp(nscale*d2 - 4.5*(1-cos)^2); store packed; accumulate
    // wsum and the unnormalized first-iteration improvement.
    const int gx = x0+tx, gy = y0+ty;
    const int pixid = (b*Hd + gy)*Wd + gx;
    float wsum = 0.f, ix=0.f, iy=0.f, iz=0.f;
    #pragma unroll
    for (int k = 0; k < 25; k++) {
        int dy = k/5 - 2, dx = k%5 - 2;
        float4 nd = sND[cy+dy][cx+dx];
        float cosv = nix*nd.x + niy*nd.y + niz*nd.z;
        float e = 1.f - cosv;
        float w = __expf(wv[k]*nscale - 4.5f*e*e);
        wv[k] = w;
        wsum += w;
        float dot = nd.w - (nd.x*pix_ + nd.y*piy + nd.z*piz);
        float t = w*dot;
        ix += t*nd.x; iy += t*nd.y; iz += t*nd.z;
        // flush each completed group of 4 weights as one 128-bit store
        if ((k & 3) == 3)
            g_w4[(k>>2)*NP + pixid] = make_float4(wv[k-3], wv[k-2], wv[k-1], wv[k]);
    }
    g_w1[pixid] = wv[24];
    float invsum = 1.f/wsum;
    g_is[pixid] = invsum;

    const int o = b*3*HW + gy*Wd + gx;
    P1[o]      = pix_ + ix*invsum;
    P1[o+HW]   = piy  + iy*invsum;
    P1[o+2*HW] = piz  + iz*invsum;
}

// ---------------------------------------------------------------------------
// k_iter: P_out = P_cur + invsum * sum_k w_k (D_k - N_k.P_i) N_k
// Weights preloaded via 6x LDG.128 + 1x LDG.32.
// LAST applies the sign(|pts_orig|) mask and writes the final output.
// ---------------------------------------------------------------------------
template<bool LAST>
__global__ __launch_bounds__(256) void k_iter(const float* __restrict__ Pcur,
                                              const float* __restrict__ nrm,
                                              const float* __restrict__ ptsOrig,
                                              float* __restrict__ Pout)
{
    __shared__ float4 sND[SHd][SWd];   // (Nx,Ny,Nz,D) with D = N.Pcur
    const int b  = blockIdx.z;
    const int x0 = blockIdx.x*TX, y0 = blockIdx.y*TY;
    const float* pb = Pcur + b*3*HW;
    const float* nb = nrm  + b*3*HW;

    for (int i = threadIdx.y*TX + threadIdx.x; i < SWd*SHd; i += TX*TY) {
        int cy = i/SWd, cx = i - cy*SWd;
        int gx = x0+cx-HALO, gy = y0+cy-HALO;
        float px=0.f,py=0.f,pz=0.f,nx=0.f,ny=0.f,nz=0.f;
        if ((unsigned)gx < Wd && (unsigned)gy < Hd) {
            int o = gy*Wd + gx;
            px = pb[o]; py = pb[o+HW]; pz = pb[o+2*HW];
            nx = nb[o]; ny = nb[o+HW]; nz = nb[o+2*HW];
        }
        sND[cy][cx] = make_float4(nx,ny,nz, px*nx + py*ny + pz*nz);
    }
    __syncthreads();

    const int tx = threadIdx.x, ty = threadIdx.y;
    const int cx = tx+HALO,   cy = ty+HALO;
    const int gx = x0+tx,     gy = y0+ty;
    const int o  = b*3*HW + gy*Wd + gx;
    const float pix_ = Pcur[o], piy = Pcur[o+HW], piz = Pcur[o+2*HW]; // L1 hits
    const int pixid = (b*Hd + gy)*Wd + gx;

    // Preload all 25 weights (coalesced vector loads, high MLP)
    float wv[25];
    #pragma unroll
    for (int kg = 0; kg < 6; kg++) {
        float4 q = g_w4[kg*NP + pixid];
        wv[kg*4+0]=q.x; wv[kg*4+1]=q.y; wv[kg*4+2]=q.z; wv[kg*4+3]=q.w;
    }
    wv[24] = g_w1[pixid];
    const float invsum = g_is[pixid];

    float ix=0.f, iy=0.f, iz=0.f;
    #pragma unroll
    for (int k = 0; k < 25; k++) {
        int dy = k/5 - 2, dx = k%5 - 2;
        float4 nd = sND[cy+dy][cx+dx];
        float dot = nd.w - (nd.x*pix_ + nd.y*piy + nd.z*piz);
        float t = wv[k]*dot;
        ix += t*nd.x; iy += t*nd.y; iz += t*nd.z;
    }
    float ox = pix_ + ix*invsum, oy = piy + iy*invsum, oz = piz + iz*invsum;
    if (LAST) {
        ox = (ptsOrig[o]      != 0.f) ? ox : 0.f;
        oy = (ptsOrig[o+HW]   != 0.f) ? oy : 0.f;
        oz = (ptsOrig[o+2*HW] != 0.f) ? oz : 0.f;
    }
    Pout[o] = ox; Pout[o+HW] = oy; Pout[o+2*HW] = oz;
}

extern "C" void kernel_launch(void* const* d_in, const int* in_sizes, int n_in,
                              void* d_out, int out_size)
{
    const float* pts = (const float*)d_in[0];
    const float* nrm = (const float*)d_in[1];
    float* out = (float*)d_out;

    float *PA, *PB;
    cudaGetSymbolAddress((void**)&PA, g_PA);
    cudaGetSymbolAddress((void**)&PB, g_PB);

    dim3 block(TX, TY);
    dim3 grid(Wd/TX, Hd/TY, Bd);   // 16 x 32 x 4

    k_pre<<<grid, block>>>(pts, nrm, PA);                 // weights + iter 1
    k_iter<false><<<grid, block>>>(PA, nrm, pts, PB);     // iter 2
    k_iter<true ><<<grid, block>>>(PB, nrm, pts, out);    // iter 3 + mask
}

// round 7
// speedup vs baseline: 1.3852x; 1.0114x over previous
#include <cuda_runtime.h>

#define Wd 512
#define Hd 256
#define Bd 4
#define HW (Hd*Wd)
#define NP (Bd*HW)
#define TX 32
#define TY 8
#define HALO 2
#define SWd (TX+2*HALO)   // 36
#define SHd (TY+2*HALO)   // 12

// Scratch (static __device__ arrays; no cudaMalloc allowed)
__device__ float4 g_w4[6*NP];  // weights k=0..23 packed as float4 planes
__device__ float  g_w1[NP];    // weight k=24
__device__ float  g_is[NP];    // 1/sum(w)
__device__ float  g_PA[3*NP];
__device__ float  g_PB[3*NP];

// ---------------------------------------------------------------------------
// k_pre: bilateral weights (stored raw + invsum) and first iteration.
// No wv[25] array: pass 1 computes only maxn2; pass 2 recomputes d2 per tap
// via d2 = |Pk|^2 + |Pi|^2 - 2 Pk.Pi  (|P|^2 cached in sP.w).
// ---------------------------------------------------------------------------
__global__ __launch_bounds__(256,5) void k_pre(const float* __restrict__ pts,
                                               const float* __restrict__ nrm,
                                               float* __restrict__ P1)
{
    __shared__ float4 sP [SHd][SWd];   // (Px,Py,Pz,|P|^2)
    __shared__ float4 sND[SHd][SWd];   // (Nx,Ny,Nz,D)  D = N.P
    const int b  = blockIdx.z;
    const int x0 = blockIdx.x*TX, y0 = blockIdx.y*TY;
    const float* pb = pts + b*3*HW;
    const float* nb = nrm + b*3*HW;

    for (int i = threadIdx.y*TX + threadIdx.x; i < SWd*SHd; i += TX*TY) {
        int cy = i/SWd, cx = i - cy*SWd;
        int gx = x0+cx-HALO, gy = y0+cy-HALO;
        float px=0.f,py=0.f,pz=0.f,nx=0.f,ny=0.f,nz=0.f;
        if ((unsigned)gx < Wd && (unsigned)gy < Hd) {
            int o = gy*Wd + gx;
            px = pb[o]; py = pb[o+HW]; pz = pb[o+2*HW];
            nx = nb[o]; ny = nb[o+HW]; nz = nb[o+2*HW];
        }
        sP [cy][cx] = make_float4(px,py,pz, px*px + py*py + pz*pz);
        sND[cy][cx] = make_float4(nx,ny,nz, px*nx + py*ny + pz*nz);
    }
    __syncthreads();

    const int tx = threadIdx.x, ty = threadIdx.y;
    const int cx = tx+HALO,   cy = ty+HALO;
    const float4 pc = sP[cy][cx];
    const float4 nc = sND[cy][cx];
    const float pix_ = pc.x, piy = pc.y, piz = pc.z, pi2 = pc.w;
    const float nix  = nc.x, niy = nc.y, niz = nc.z;

    // Pass 1: only the max squared distance (for sigma_c); nothing stored.
    float maxn2 = 0.f;
    #pragma unroll
    for (int k = 0; k < 25; k++) {
        int dy = k/5 - 2, dx = k%5 - 2;
        float4 p = sP[cy+dy][cx+dx];
        float d2 = (p.w + pi2) - 2.f*(p.x*pix_ + p.y*piy + p.z*piz);
        maxn2 = fmaxf(maxn2, d2);
    }
    float sig    = sqrtf(maxn2)*0.2f + 1e-5f;
    float nscale = -0.5f/(sig*sig);

    // Pass 2: recompute d2, w = exp(nscale*d2 - 4.5*(1-cos)^2);
    // stage 4 weights at a time for 128-bit stores; accumulate wsum + imp0.
    const int gx = x0+tx, gy = y0+ty;
    const int pixid = (b*Hd + gy)*Wd + gx;
    float wsum = 0.f, ix=0.f, iy=0.f, iz=0.f;
    float s0=0.f, s1=0.f, s2=0.f;   // staging for the current group of 4
    #pragma unroll
    for (int k = 0; k < 25; k++) {
        int dy = k/5 - 2, dx = k%5 - 2;
        float4 p  = sP [cy+dy][cx+dx];
        float4 nd = sND[cy+dy][cx+dx];
        float d2   = (p.w + pi2) - 2.f*(p.x*pix_ + p.y*piy + p.z*piz);
        float cosv = nix*nd.x + niy*nd.y + niz*nd.z;
        float e = 1.f - cosv;
        float w = __expf(d2*nscale - 4.5f*e*e);
        wsum += w;
        float dot = nd.w - (nd.x*pix_ + nd.y*piy + nd.z*piz);
        float t = w*dot;
        ix += t*nd.x; iy += t*nd.y; iz += t*nd.z;
        int j = k & 3;
        if (k == 24)      g_w1[pixid] = w;
        else if (j == 0)  s0 = w;
        else if (j == 1)  s1 = w;
        else if (j == 2)  s2 = w;
        else              g_w4[(k>>2)*NP + pixid] = make_float4(s0, s1, s2, w);
    }
    float invsum = 1.f/wsum;
    g_is[pixid] = invsum;

    const int o = b*3*HW + gy*Wd + gx;
    P1[o]      = pix_ + ix*invsum;
    P1[o+HW]   = piy  + iy*invsum;
    P1[o+2*HW] = piz  + iz*invsum;
}

// ---------------------------------------------------------------------------
// k_iter: P_out = P_cur + invsum * sum_k w_k (D_k - N_k.P_i) N_k
// Weights streamed one float4 per 4 taps (low register liveness).
// ---------------------------------------------------------------------------
template<bool LAST>
__global__ __launch_bounds__(256,6) void k_iter(const float* __restrict__ Pcur,
                                                const float* __restrict__ nrm,
                                                const float* __restrict__ ptsOrig,
                                                float* __restrict__ Pout)
{
    __shared__ float4 sND[SHd][SWd];   // (Nx,Ny,Nz,D) with D = N.Pcur
    const int b  = blockIdx.z;
    const int x0 = blockIdx.x*TX, y0 = blockIdx.y*TY;
    const float* pb = Pcur + b*3*HW;
    const float* nb = nrm  + b*3*HW;

    for (int i = threadIdx.y*TX + threadIdx.x; i < SWd*SHd; i += TX*TY) {
        int cy = i/SWd, cx = i - cy*SWd;
        int gx = x0+cx-HALO, gy = y0+cy-HALO;
        float px=0.f,py=0.f,pz=0.f,nx=0.f,ny=0.f,nz=0.f;
        if ((unsigned)gx < Wd && (unsigned)gy < Hd) {
            int o = gy*Wd + gx;
            px = pb[o]; py = pb[o+HW]; pz = pb[o+2*HW];
            nx = nb[o]; ny = nb[o+HW]; nz = nb[o+2*HW];
        }
        sND[cy][cx] = make_float4(nx,ny,nz, px*nx + py*ny + pz*nz);
    }
    __syncthreads();

    const int tx = threadIdx.x, ty = threadIdx.y;
    const int cx = tx+HALO,   cy = ty+HALO;
    const int gx = x0+tx,     gy = y0+ty;
    const int o  = b*3*HW + gy*Wd + gx;
    const float pix_ = Pcur[o], piy = Pcur[o+HW], piz = Pcur[o+2*HW]; // L1 hits
    const int pixid = (b*Hd + gy)*Wd + gx;
    const float invsum = g_is[pixid];

    float ix=0.f, iy=0.f, iz=0.f;
    #pragma unroll
    for (int kg = 0; kg < 6; kg++) {
        float4 q = g_w4[kg*NP + pixid];
        #pragma unroll
        for (int j = 0; j < 4; j++) {
            int k = kg*4 + j;
            int dy = k/5 - 2, dx = k%5 - 2;
            float w = (j==0)?q.x:(j==1)?q.y:(j==2)?q.z:q.w;
            float4 nd = sND[cy+dy][cx+dx];
            float dot = nd.w - (nd.x*pix_ + nd.y*piy + nd.z*piz);
            float t = w*dot;
            ix += t*nd.x; iy += t*nd.y; iz += t*nd.z;
        }
    }
    {   // tap 24 (dy=+2, dx=+2)
        float w = g_w1[pixid];
        float4 nd = sND[cy+2][cx+2];
        float dot = nd.w - (nd.x*pix_ + nd.y*piy + nd.z*piz);
        float t = w*dot;
        ix += t*nd.x; iy += t*nd.y; iz += t*nd.z;
    }
    float ox = pix_ + ix*invsum, oy = piy + iy*invsum, oz = piz + iz*invsum;
    if (LAST) {
        ox = (ptsOrig[o]      != 0.f) ? ox : 0.f;
        oy = (ptsOrig[o+HW]   != 0.f) ? oy : 0.f;
        oz = (ptsOrig[o+2*HW] != 0.f) ? oz : 0.f;
    }
    Pout[o] = ox; Pout[o+HW] = oy; Pout[o+2*HW] = oz;
}

extern "C" void kernel_launch(void* const* d_in, const int* in_sizes, int n_in,
                              void* d_out, int out_size)
{
    const float* pts = (const float*)d_in[0];
    const float* nrm = (const float*)d_in[1];
    float* out = (float*)d_out;

    float *PA, *PB;
    cudaGetSymbolAddress((void**)&PA, g_PA);
    cudaGetSymbolAddress((void**)&PB, g_PB);

    dim3 block(TX, TY);
    dim3 grid(Wd/TX, Hd/TY, Bd);   // 16 x 32 x 4

    k_pre<<<grid, block>>>(pts, nrm, PA);                 // weights + iter 1
    k_iter<false><<<grid, block>>>(PA, nrm, pts, PB);     // iter 2
    k_iter<true ><<<grid, block>>>(PB, nrm, pts, out);    // iter 3 + mask
}

// round 12
// speedup vs baseline: 1.3860x; 1.0006x over previous
#include <cuda_runtime.h>
#include <cstdint>

#define Wd 512
#define Hd 256
#define Bd 4
#define HW (Hd*Wd)
#define NP (Bd*HW)
#define TX 32
#define TY 8
#define HALO 2
#define SWd (TX+2*HALO)   // 36
#define SHd (TY+2*HALO)   // 12

// Scratch (static __device__ arrays; no cudaMalloc allowed)
__device__ float4 g_w4[6*NP];  // weights k=0..23 packed as float4 planes
__device__ float  g_w1[NP];    // weight k=24
__device__ float  g_is[NP];    // 1/sum(w)
__device__ float  g_PA[3*NP];
__device__ float  g_PB[3*NP];

// ---------------------------------------------------------------------------
// k_pre: bilateral weights (raw fp32 + invsum) and first iteration.
// Pass 1 computes only maxn2; pass 2 recomputes d2 via |Pk|^2+|Pi|^2-2Pk.Pi.
// (Best measured shape: 24.9us, 48 regs, occ 56%.)
// ---------------------------------------------------------------------------
__global__ __launch_bounds__(256,5) void k_pre(const float* __restrict__ pts,
                                               const float* __restrict__ nrm,
                                               float* __restrict__ P1)
{
    __shared__ float4 sP [SHd][SWd];   // (Px,Py,Pz,|P|^2)
    __shared__ float4 sND[SHd][SWd];   // (Nx,Ny,Nz,D)  D = N.P
    const int b  = blockIdx.z;
    const int x0 = blockIdx.x*TX, y0 = blockIdx.y*TY;
    const float* pb = pts + b*3*HW;
    const float* nb = nrm + b*3*HW;

    for (int i = threadIdx.y*TX + threadIdx.x; i < SWd*SHd; i += TX*TY) {
        int cy = i/SWd, cx = i - cy*SWd;
        int gx = x0+cx-HALO, gy = y0+cy-HALO;
        float px=0.f,py=0.f,pz=0.f,nx=0.f,ny=0.f,nz=0.f;
        if ((unsigned)gx < Wd && (unsigned)gy < Hd) {
            int o = gy*Wd + gx;
            px = pb[o]; py = pb[o+HW]; pz = pb[o+2*HW];
            nx = nb[o]; ny = nb[o+HW]; nz = nb[o+2*HW];
        }
        sP [cy][cx] = make_float4(px,py,pz, px*px + py*py + pz*pz);
        sND[cy][cx] = make_float4(nx,ny,nz, px*nx + py*ny + pz*nz);
    }
    __syncthreads();

    const int tx = threadIdx.x, ty = threadIdx.y;
    const int cx = tx+HALO,   cy = ty+HALO;
    const float4 pc = sP[cy][cx];
    const float4 nc = sND[cy][cx];
    const float pix_ = pc.x, piy = pc.y, piz = pc.z, pi2 = pc.w;
    const float nix  = nc.x, niy = nc.y, niz = nc.z;

    // Pass 1: only max squared distance (sigma_c)
    float maxn2 = 0.f;
    #pragma unroll
    for (int k = 0; k < 25; k++) {
        int dy = k/5 - 2, dx = k%5 - 2;
        float4 p = sP[cy+dy][cx+dx];
        float d2 = (p.w + pi2) - 2.f*(p.x*pix_ + p.y*piy + p.z*piz);
        maxn2 = fmaxf(maxn2, d2);
    }
    float sig    = sqrtf(maxn2)*0.2f + 1e-5f;
    float nscale = -0.5f/(sig*sig);

    // Pass 2: w = exp(nscale*d2 - 4.5*(1-cos)^2); stage groups of 4 for
    // 128-bit stores; accumulate wsum + unnormalized first-iter improvement.
    const int gx = x0+tx, gy = y0+ty;
    const int pixid = (b*Hd + gy)*Wd + gx;
    float wsum = 0.f, ix=0.f, iy=0.f, iz=0.f;
    float s0=0.f, s1=0.f, s2=0.f;
    #pragma unroll
    for (int k = 0; k < 25; k++) {
        int dy = k/5 - 2, dx = k%5 - 2;
        float4 p  = sP [cy+dy][cx+dx];
        float4 nd = sND[cy+dy][cx+dx];
        float d2   = (p.w + pi2) - 2.f*(p.x*pix_ + p.y*piy + p.z*piz);
        float cosv = nix*nd.x + niy*nd.y + niz*nd.z;
        float e = 1.f - cosv;
        float w = __expf(d2*nscale - 4.5f*e*e);
        wsum += w;
        float dot = nd.w - (nd.x*pix_ + nd.y*piy + nd.z*piz);
        float t = w*dot;
        ix += t*nd.x; iy += t*nd.y; iz += t*nd.z;
        int j = k & 3;
        if (k == 24)      g_w1[pixid] = w;
        else if (j == 0)  s0 = w;
        else if (j == 1)  s1 = w;
        else if (j == 2)  s2 = w;
        else              g_w4[(k>>2)*NP + pixid] = make_float4(s0, s1, s2, w);
    }
    float invsum = 1.f/wsum;
    g_is[pixid] = invsum;

    const int o = b*3*HW + gy*Wd + gx;
    P1[o]      = pix_ + ix*invsum;
    P1[o+HW]   = piy  + iy*invsum;
    P1[o+2*HW] = piz  + iz*invsum;
}

// ---------------------------------------------------------------------------
// Tap helper (template K -> compile-time smem offsets).
// ---------------------------------------------------------------------------
struct Acc { float x, y, z; };

template<int K>
static __device__ __forceinline__ void tap(Acc& a, float wgt,
                                           const float4 (*snd)[SWd],
                                           int cy, int cx,
                                           float pix_, float piy, float piz)
{
    constexpr int dy = K/5 - 2;
    constexpr int dx = K%5 - 2;
    float4 nd = snd[cy+dy][cx+dx];
    float dot = nd.w - (nd.x*pix_ + nd.y*piy + nd.z*piz);
    float t = wgt*dot;
    a.x += t*nd.x; a.y += t*nd.y; a.z += t*nd.z;
}

template<int KG>
static __device__ __forceinline__ void quad(Acc& a, float4 q,
                                            const float4 (*snd)[SWd],
                                            int cy, int cx,
                                            float pix_, float piy, float piz)
{
    tap<KG*4+0>(a, q.x, snd, cy, cx, pix_, piy, piz);
    tap<KG*4+1>(a, q.y, snd, cy, cx, pix_, piy, piz);
    tap<KG*4+2>(a, q.z, snd, cy, cx, pix_, piy, piz);
    tap<KG*4+3>(a, q.w, snd, cy, cx, pix_, piy, piz);
}

// ---------------------------------------------------------------------------
// k_iter: P_out = P_cur + invsum * sum_k w_k (D_k - N_k.P_i) N_k
// fp32 weights; ALL weight loads issued BEFORE the tile-fill loop so their
// L2 latency overlaps the fill + barrier.
// ---------------------------------------------------------------------------
template<bool LAST>
__global__ __launch_bounds__(256,4) void k_iter(const float* __restrict__ Pcur,
                                                const float* __restrict__ nrm,
                                                const float* __restrict__ ptsOrig,
                                                float* __restrict__ Pout)
{
    __shared__ float4 sND[SHd][SWd];   // (Nx,Ny,Nz,D) with D = N.Pcur
    const int b  = blockIdx.z;
    const int x0 = blockIdx.x*TX, y0 = blockIdx.y*TY;
    const int tx = threadIdx.x, ty = threadIdx.y;
    const int gx = x0+tx,       gy = y0+ty;
    const int pixid = (b*Hd + gy)*Wd + gx;

    // ---- prefetch weights first: L2 latency overlaps the fill below ----
    const float4 q0 = g_w4[0*NP + pixid];
    const float4 q1 = g_w4[1*NP + pixid];
    const float4 q2 = g_w4[2*NP + pixid];
    const float4 q3 = g_w4[3*NP + pixid];
    const float4 q4 = g_w4[4*NP + pixid];
    const float4 q5 = g_w4[5*NP + pixid];
    const float w24 = g_w1[pixid];
    const float invsum = g_is[pixid];

    const float* pb = Pcur + b*3*HW;
    const float* nb = nrm  + b*3*HW;

    for (int i = ty*TX + tx; i < SWd*SHd; i += TX*TY) {
        int cy = i/SWd, cx = i - cy*SWd;
        int hx = x0+cx-HALO, hy = y0+cy-HALO;
        float px=0.f,py=0.f,pz=0.f,nx=0.f,ny=0.f,nz=0.f;
        if ((unsigned)hx < Wd && (unsigned)hy < Hd) {
            int o = hy*Wd + hx;
            px = pb[o]; py = pb[o+HW]; pz = pb[o+2*HW];
            nx = nb[o]; ny = nb[o+HW]; nz = nb[o+2*HW];
        }
        sND[cy][cx] = make_float4(nx,ny,nz, px*nx + py*ny + pz*nz);
    }
    __syncthreads();

    const int cx = tx+HALO, cy = ty+HALO;
    const int o  = b*3*HW + gy*Wd + gx;
    const float pix_ = Pcur[o], piy = Pcur[o+HW], piz = Pcur[o+2*HW]; // L1 hits

    Acc a = {0.f, 0.f, 0.f};
    quad<0>(a, q0, sND, cy, cx, pix_, piy, piz);
    quad<1>(a, q1, sND, cy, cx, pix_, piy, piz);
    quad<2>(a, q2, sND, cy, cx, pix_, piy, piz);
    quad<3>(a, q3, sND, cy, cx, pix_, piy, piz);
    quad<4>(a, q4, sND, cy, cx, pix_, piy, piz);
    quad<5>(a, q5, sND, cy, cx, pix_, piy, piz);
    tap<24>(a, w24, sND, cy, cx, pix_, piy, piz);

    float ox = pix_ + a.x*invsum, oy = piy + a.y*invsum, oz = piz + a.z*invsum;
    if (LAST) {
        ox = (ptsOrig[o]      != 0.f) ? ox : 0.f;
        oy = (ptsOrig[o+HW]   != 0.f) ? oy : 0.f;
        oz = (ptsOrig[o+2*HW] != 0.f) ? oz : 0.f;
    }
    Pout[o] = ox; Pout[o+HW] = oy; Pout[o+2*HW] = oz;
}

extern "C" void kernel_launch(void* const* d_in, const int* in_sizes, int n_in,
                              void* d_out, int out_size)
{
    const float* pts = (const float*)d_in[0];
    const float* nrm = (const float*)d_in[1];
    float* out = (float*)d_out;

    float *PA, *PB;
    cudaGetSymbolAddress((void**)&PA, g_PA);
    cudaGetSymbolAddress((void**)&PB, g_PB);

    dim3 block(TX, TY);
    dim3 grid(Wd/TX, Hd/TY, Bd);   // 16 x 32 x 4

    k_pre<<<grid, block>>>(pts, nrm, PA);                 // weights + iter 1
    k_iter<false><<<grid, block>>>(PA, nrm, pts, PB);     // iter 2
    k_iter<true ><<<grid, block>>>(PB, nrm, pts, out);    // iter 3 + mask
}

// round 13
// speedup vs baseline: 1.4442x; 1.0420x over previous
#include <cuda_runtime.h>

#define Wd 512
#define Hd 256
#define Bd 4
#define HW (Hd*Wd)
#define NP (Bd*HW)
#define TX 32
#define TY 8
#define VY 2
#define TILEH (TY*VY)      // 16
#define SW (TX+4)          // 36
#define SH (TILEH+4)       // 20

// Scratch (static __device__ arrays; no cudaMalloc allowed)
__device__ float4 g_w4[6*NP];  // weights k=0..23 packed as float4 planes
__device__ float  g_w1[NP];    // weight k=24
__device__ float  g_is[NP];    // 1/sum(w)
__device__ float  g_PA[3*NP];
__device__ float  g_PB[3*NP];

// ---------------------------------------------------------------------------
// k_pre: V=2 pixels/thread. Bilateral weights (raw fp32 + invsum) + iter 1.
// No per-tap arrays: pass 1 computes only maxn2; pass 2 recomputes d2 via
// |Pk|^2+|Pi|^2-2Pk.Pi and streams weight stores through 3 staging regs.
// ---------------------------------------------------------------------------
__global__ __launch_bounds__(256,4) void k_pre(const float* __restrict__ pts,
                                               const float* __restrict__ nrm,
                                               float* __restrict__ P1)
{
    __shared__ float4 sP [SH][SW];   // (Px,Py,Pz,|P|^2)
    __shared__ float4 sND[SH][SW];   // (Nx,Ny,Nz,D)  D = N.P
    const int b  = blockIdx.z;
    const int x0 = blockIdx.x*TX, y0 = blockIdx.y*TILEH;
    const float* pb = pts + b*3*HW;
    const float* nb = nrm + b*3*HW;

    for (int i = threadIdx.y*TX + threadIdx.x; i < SW*SH; i += TX*TY) {
        int cy = i/SW, cx = i - cy*SW;
        int gx = x0+cx-2, gy = y0+cy-2;
        float px=0.f,py=0.f,pz=0.f,nx=0.f,ny=0.f,nz=0.f;
        if ((unsigned)gx < Wd && (unsigned)gy < Hd) {
            int o = gy*Wd + gx;
            px = pb[o]; py = pb[o+HW]; pz = pb[o+2*HW];
            nx = nb[o]; ny = nb[o+HW]; nz = nb[o+2*HW];
        }
        sP [cy][cx] = make_float4(px,py,pz, px*px + py*py + pz*pz);
        sND[cy][cx] = make_float4(nx,ny,nz, px*nx + py*ny + pz*nz);
    }
    __syncthreads();

    const int tx = threadIdx.x, ty = threadIdx.y;
    const int r0 = ty*VY;               // tile-local top row of this pair

    // centers (pixel A = row r0, pixel B = row r0+1)
    const float4 pcA = sP [r0+2][tx+2], pcB = sP [r0+3][tx+2];
    const float4 ncA = sND[r0+2][tx+2], ncB = sND[r0+3][tx+2];

    // Pass 1: max squared distance per pixel (shared row reads serve both)
    float maxA = 0.f, maxB = 0.f;
    #pragma unroll
    for (int j = 0; j < 6; j++) {
        #pragma unroll
        for (int dx = 0; dx < 5; dx++) {
            float4 p = sP[r0+j][tx+dx];
            if (j <= 4) {
                float d2 = (p.w + pcA.w) - 2.f*(p.x*pcA.x + p.y*pcA.y + p.z*pcA.z);
                maxA = fmaxf(maxA, d2);
            }
            if (j >= 1) {
                float d2 = (p.w + pcB.w) - 2.f*(p.x*pcB.x + p.y*pcB.y + p.z*pcB.z);
                maxB = fmaxf(maxB, d2);
            }
        }
    }
    float sigA = sqrtf(maxA)*0.2f + 1e-5f;
    float sigB = sqrtf(maxB)*0.2f + 1e-5f;
    float nsA = -0.5f/(sigA*sigA);
    float nsB = -0.5f/(sigB*sigB);

    // Pass 2: recompute d2, w = exp(ns*d2 - 4.5*(1-cos)^2); stage groups of 4
    // for 128-bit stores; accumulate wsum + unnormalized improvement.
    const int gx = x0+tx;
    const int gyA = y0+r0, gyB = gyA+1;
    const int idA = (b*Hd + gyA)*Wd + gx;
    const int idB = idA + Wd;
    float wsA=0.f, axA=0.f, ayA=0.f, azA=0.f, a0=0.f, a1=0.f, a2=0.f;
    float wsB=0.f, axB=0.f, ayB=0.f, azB=0.f, b0=0.f, b1=0.f, b2=0.f;
    #pragma unroll
    for (int j = 0; j < 6; j++) {
        #pragma unroll
        for (int dx = 0; dx < 5; dx++) {
            float4 p  = sP [r0+j][tx+dx];
            float4 nd = sND[r0+j][tx+dx];
            if (j <= 4) {
                int k = j*5 + dx;
                float d2   = (p.w + pcA.w) - 2.f*(p.x*pcA.x + p.y*pcA.y + p.z*pcA.z);
                float cosv = ncA.x*nd.x + ncA.y*nd.y + ncA.z*nd.z;
                float e = 1.f - cosv;
                float w = __expf(d2*nsA - 4.5f*e*e);
                wsA += w;
                float dot = nd.w - (nd.x*pcA.x + nd.y*pcA.y + nd.z*pcA.z);
                float t = w*dot;
                axA += t*nd.x; ayA += t*nd.y; azA += t*nd.z;
                int m = k & 3;
                if (k == 24)     g_w1[idA] = w;
                else if (m == 0) a0 = w;
                else if (m == 1) a1 = w;
                else if (m == 2) a2 = w;
                else             g_w4[(k>>2)*NP + idA] = make_float4(a0,a1,a2,w);
            }
            if (j >= 1) {
                int k = (j-1)*5 + dx;
                float d2   = (p.w + pcB.w) - 2.f*(p.x*pcB.x + p.y*pcB.y + p.z*pcB.z);
                float cosv = ncB.x*nd.x + ncB.y*nd.y + ncB.z*nd.z;
                float e = 1.f - cosv;
                float w = __expf(d2*nsB - 4.5f*e*e);
                wsB += w;
                float dot = nd.w - (nd.x*pcB.x + nd.y*pcB.y + nd.z*pcB.z);
                float t = w*dot;
                axB += t*nd.x; ayB += t*nd.y; azB += t*nd.z;
                int m = k & 3;
                if (k == 24)     g_w1[idB] = w;
                else if (m == 0) b0 = w;
                else if (m == 1) b1 = w;
                else if (m == 2) b2 = w;
                else             g_w4[(k>>2)*NP + idB] = make_float4(b0,b1,b2,w);
            }
        }
    }
    float isA = 1.f/wsA, isB = 1.f/wsB;
    g_is[idA] = isA;
    g_is[idB] = isB;

    const int oA = b*3*HW + gyA*Wd + gx;
    const int oB = oA + Wd;
    P1[oA]      = pcA.x + axA*isA;
    P1[oA+HW]   = pcA.y + ayA*isA;
    P1[oA+2*HW] = pcA.z + azA*isA;
    P1[oB]      = pcB.x + axB*isB;
    P1[oB+HW]   = pcB.y + ayB*isB;
    P1[oB+2*HW] = pcB.z + azB*isB;
}

// ---------------------------------------------------------------------------
// k_iter: V=2 pixels/thread. P_out = P_cur + invsum*sum_k w_k(D_k-N_k.P_i)N_k
// Weights streamed one float4 per 4 taps per pixel (low liveness).
// ---------------------------------------------------------------------------
template<bool LAST>
__global__ __launch_bounds__(256,4) void k_iter(const float* __restrict__ Pcur,
                                                const float* __restrict__ nrm,
                                                const float* __restrict__ ptsOrig,
                                                float* __restrict__ Pout)
{
    __shared__ float4 sND[SH][SW];   // (Nx,Ny,Nz,D) with D = N.Pcur
    const int b  = blockIdx.z;
    const int x0 = blockIdx.x*TX, y0 = blockIdx.y*TILEH;
    const float* pb = Pcur + b*3*HW;
    const float* nb = nrm  + b*3*HW;

    for (int i = threadIdx.y*TX + threadIdx.x; i < SW*SH; i += TX*TY) {
        int cy = i/SW, cx = i - cy*SW;
        int gx = x0+cx-2, gy = y0+cy-2;
        float px=0.f,py=0.f,pz=0.f,nx=0.f,ny=0.f,nz=0.f;
        if ((unsigned)gx < Wd && (unsigned)gy < Hd) {
            int o = gy*Wd + gx;
            px = pb[o]; py = pb[o+HW]; pz = pb[o+2*HW];
            nx = nb[o]; ny = nb[o+HW]; nz = nb[o+2*HW];
        }
        sND[cy][cx] = make_float4(nx,ny,nz, px*nx + py*ny + pz*nz);
    }
    __syncthreads();

    const int tx = threadIdx.x, ty = threadIdx.y;
    const int r0 = ty*VY;
    const int gx = x0+tx;
    const int gyA = y0+r0;
    const int idA = (b*Hd + gyA)*Wd + gx;
    const int idB = idA + Wd;
    const int oA  = b*3*HW + gyA*Wd + gx;
    const int oB  = oA + Wd;

    const float pAx = Pcur[oA],    pAy = Pcur[oA+HW],    pAz = Pcur[oA+2*HW];
    const float pBx = Pcur[oB],    pBy = Pcur[oB+HW],    pBz = Pcur[oB+2*HW];
    const float isA = g_is[idA],   isB = g_is[idB];

    float axA=0.f, ayA=0.f, azA=0.f;
    float axB=0.f, ayB=0.f, azB=0.f;
    float4 qA = make_float4(0,0,0,0), qB = make_float4(0,0,0,0);
    #pragma unroll
    for (int j = 0; j < 6; j++) {
        #pragma unroll
        for (int dx = 0; dx < 5; dx++) {
            float4 nd = sND[r0+j][tx+dx];
            if (j <= 4) {
                int k = j*5 + dx;
                float w;
                if (k == 24) w = g_w1[idA];
                else {
                    int m = k & 3;
                    if (m == 0) qA = g_w4[(k>>2)*NP + idA];
                    w = (m==0)?qA.x:(m==1)?qA.y:(m==2)?qA.z:qA.w;
                }
                float dot = nd.w - (nd.x*pAx + nd.y*pAy + nd.z*pAz);
                float t = w*dot;
                axA += t*nd.x; ayA += t*nd.y; azA += t*nd.z;
            }
            if (j >= 1) {
                int k = (j-1)*5 + dx;
                float w;
                if (k == 24) w = g_w1[idB];
                else {
                    int m = k & 3;
                    if (m == 0) qB = g_w4[(k>>2)*NP + idB];
                    w = (m==0)?qB.x:(m==1)?qB.y:(m==2)?qB.z:qB.w;
                }
                float dot = nd.w - (nd.x*pBx + nd.y*pBy + nd.z*pBz);
                float t = w*dot;
                axB += t*nd.x; ayB += t*nd.y; azB += t*nd.z;
            }
        }
    }

    float oxA = pAx + axA*isA, oyA = pAy + ayA*isA, ozA = pAz + azA*isA;
    float oxB = pBx + axB*isB, oyB = pBy + ayB*isB, ozB = pBz + azB*isB;
    if (LAST) {
        oxA = (ptsOrig[oA]      != 0.f) ? oxA : 0.f;
        oyA = (ptsOrig[oA+HW]   != 0.f) ? oyA : 0.f;
        ozA = (ptsOrig[oA+2*HW] != 0.f) ? ozA : 0.f;
        oxB = (ptsOrig[oB]      != 0.f) ? oxB : 0.f;
        oyB = (ptsOrig[oB+HW]   != 0.f) ? oyB : 0.f;
        ozB = (ptsOrig[oB+2*HW] != 0.f) ? ozB : 0.f;
    }
    Pout[oA] = oxA; Pout[oA+HW] = oyA; Pout[oA+2*HW] = ozA;
    Pout[oB] = oxB; Pout[oB+HW] = oyB; Pout[oB+2*HW] = ozB;
}

extern "C" void kernel_launch(void* const* d_in, const int* in_sizes, int n_in,
                              void* d_out, int out_size)
{
    const float* pts = (const float*)d_in[0];
    const float* nrm = (const float*)d_in[1];
    float* out = (float*)d_out;

    float *PA, *PB;
    cudaGetSymbolAddress((void**)&PA, g_PA);
    cudaGetSymbolAddress((void**)&PB, g_PB);

    dim3 block(TX, TY);
    dim3 grid(Wd/TX, Hd/TILEH, Bd);   // 16 x 16 x 4

    k_pre<<<grid, block>>>(pts, nrm, PA);                 // weights + iter 1
    k_iter<false><<<grid, block>>>(PA, nrm, pts, PB);     // iter 2
    k_iter<true ><<<grid, block>>>(PB, nrm, pts, out);    // iter 3 + mask
}